// round 12
// baseline (speedup 1.0000x reference)
#include <cuda_runtime.h>
#include <cuda_bf16.h>
#include <cstdint>

#define HASH_SIZE 10240
#define HMOD      10239
#define PROJ_DIM  128
#define MODEL_DIM 512
#define N_TOKENS  (8 * 8192)

// 21 MB scratch: projected embedding table P[hash][model_dim].
// Written by kernel 1 with default (L2-allocating) stores; read by kernel 2
// as L2 hits. Do NOT stream these stores.
__device__ float g_P[HASH_SIZE * MODEL_DIM];

// packed fp32x2 FMA (sm_100+ PTX only; ptxas never auto-fuses this)
__device__ __forceinline__ void ffma2(unsigned long long& d,
                                      unsigned long long a,
                                      unsigned long long b) {
    asm("fma.rn.f32x2 %0, %1, %2, %0;" : "+l"(d) : "l"(a), "l"(b));
}

// ---------------------------------------------------------------------------
// Kernel 1: P[h][m] = scale * sum_k embed[h][k] * proj[m][k]
//   A = embed [10240,128] row-major (k contiguous)
//   B = proj  [512,128]   row-major (k contiguous)
// Block tile 128(h) x 64(m), 256 threads, thread tile 8x4, K packed in f32x2
// pairs. Per warp per k-pair: 32 FFMA2 vs 12 LDS.64 -> LDS crossbar demand is
// 0.75 of FFMA-pipe cycles (25% slack -> cleanly FFMA-bound).
// Row pad = 130 floats: b-read lanes hit 16 distinct 8B bank-pairs
// (conflict-free); a-reads are 2-way broadcast (free). Row stride 520 B is
// 8B-aligned for the u64 loads.
// ---------------------------------------------------------------------------
#define TILE_H    128
#define TILE_M    64
#define ROWPAD    130
#define GEMM_SMEM ((TILE_H + TILE_M) * ROWPAD * (int)sizeof(float))

__global__ __launch_bounds__(256, 2) void bigram_gemm_kernel(
    const float* __restrict__ A, const float* __restrict__ B,
    const float* __restrict__ scale_p) {
    extern __shared__ float smem[];
    float(*As)[ROWPAD] = (float(*)[ROWPAD])smem;
    float(*Bs)[ROWPAD] = (float(*)[ROWPAD])(smem + TILE_H * ROWPAD);

    const int tid = threadIdx.x;
    const int h0  = blockIdx.x * TILE_H;
    const int m0  = blockIdx.y * TILE_M;

    // Stage A tile (128 rows) + B tile (64 rows), 128 floats each, as float4.
    for (int i = tid; i < TILE_H * (PROJ_DIM / 4); i += 256) {
        int r = i >> 5, c = i & 31;
        float4 v = __ldg(&((const float4*)(A + (size_t)(h0 + r) * PROJ_DIM))[c]);
        As[r][c * 4 + 0] = v.x; As[r][c * 4 + 1] = v.y;
        As[r][c * 4 + 2] = v.z; As[r][c * 4 + 3] = v.w;
    }
    for (int i = tid; i < TILE_M * (PROJ_DIM / 4); i += 256) {
        int r = i >> 5, c = i & 31;
        float4 v = __ldg(&((const float4*)(B + (size_t)(m0 + r) * PROJ_DIM))[c]);
        Bs[r][c * 4 + 0] = v.x; Bs[r][c * 4 + 1] = v.y;
        Bs[r][c * 4 + 2] = v.z; Bs[r][c * 4 + 3] = v.w;
    }
    __syncthreads();

    const int tx = tid & 15;   // m: m0 + tx + 16*j, j<4
    const int ty = tid >> 4;   // h: h0 + ty + 16*i, i<8

    unsigned long long acc[8][4];
#pragma unroll
    for (int i = 0; i < 8; i++)
#pragma unroll
        for (int j = 0; j < 4; j++) acc[i][j] = 0ULL;

#pragma unroll 2
    for (int kp = 0; kp < PROJ_DIM / 2; ++kp) {
        unsigned long long a[8], b[4];
#pragma unroll
        for (int j = 0; j < 4; j++)
            b[j] = *(const unsigned long long*)&Bs[tx + 16 * j][2 * kp];
#pragma unroll
        for (int i = 0; i < 8; i++)
            a[i] = *(const unsigned long long*)&As[ty + 16 * i][2 * kp];
#pragma unroll
        for (int i = 0; i < 8; i++)
#pragma unroll
            for (int j = 0; j < 4; j++) ffma2(acc[i][j], a[i], b[j]);
    }

    const float s = __ldg(scale_p);
#pragma unroll
    for (int i = 0; i < 8; i++) {
        const int h = h0 + ty + 16 * i;
#pragma unroll
        for (int j = 0; j < 4; j++) {
            const int m = m0 + tx + 16 * j;
            union { unsigned long long u; float2 f; } cvt;
            cvt.u = acc[i][j];
            // default store: allocate in L2 so kernel 2's reads hit
            g_P[(size_t)h * MODEL_DIM + m] = (cvt.f.x + cvt.f.y) * s;
        }
    }
}

// ---------------------------------------------------------------------------
// Kernel 2: hash + gather. One 512-thread block handles 4 consecutive tokens
// (8 KB contiguous output). Each 128-lane group copies one 2 KB row as
// float4s (each warp: 512 B contiguous). P reads hit L2 (21 MB resident);
// output stores use .cs streaming hint (no reuse) to protect P's residency.
// LTS-bound: ~268 MB total L2 traffic (134 read + 134 write) -> ~23 us.
//
// tok_stride: 1 for int32 token_ids, 2 for int64 (little-endian low word;
// token values < 2^31 so the low word IS the value). Resolved on host from
// in_sizes[0] -- uniform branch, broadcast loads, zero hot-path cost.
// ---------------------------------------------------------------------------
__global__ __launch_bounds__(512) void bigram_gather_kernel(
    const int* __restrict__ tok, float* __restrict__ out, int tok_stride) {
    const int token = blockIdx.x * 4 + (threadIdx.x >> 7);
    const int lane  = threadIdx.x & 127;
    const int s     = token & 8191;   // S = 8192

    // Both loads are 128-lane broadcasts (L1 hits after first warp).
    const int t_cur  = __ldg(&tok[(size_t)token * tok_stride]);
    const int t_prev = (s == 0) ? 0 : __ldg(&tok[(size_t)(token - 1) * tok_stride]);

    // 36313*t and 27191*t both < 2^31 for t < 50257 -> no int32 overflow,
    // xor of non-negatives is non-negative -> plain % == jnp.mod
    int h = (s == 0) ? HMOD : (36313 * t_cur ^ 27191 * t_prev) % HMOD;

    const float4 v = __ldg((const float4*)&g_P[(size_t)h * MODEL_DIM + lane * 4]);
    __stcs((float4*)&out[(size_t)token * MODEL_DIM + lane * 4], v);
}

// ---------------------------------------------------------------------------
extern "C" void kernel_launch(void* const* d_in, const int* in_sizes, int n_in,
                              void* d_out, int out_size) {
    const int*   tok   = (const int*)d_in[0];   // [8,8192] int32 (or int64)
    const float* embed = (const float*)d_in[1]; // [10240,128] f32
    const float* proj  = (const float*)d_in[2]; // [512,128] f32
    const float* scale = (const float*)d_in[3]; // scalar f32
    float*       out   = (float*)d_out;         // [8,8192,512] f32

    // If the harness surfaces int64 tokens as raw 32-bit words, the element
    // count doubles; otherwise tokens are int32 (JAX default, x64 off).
    const int tok_stride = (in_sizes[0] >= 2 * N_TOKENS) ? 2 : 1;

    // Unconditional (no static state); not a stream op -> capture-safe.
    cudaFuncSetAttribute(bigram_gemm_kernel,
                         cudaFuncAttributeMaxDynamicSharedMemorySize,
                         GEMM_SMEM);

    dim3 gemm_grid(HASH_SIZE / TILE_H, MODEL_DIM / TILE_M);  // 80 x 8
    bigram_gemm_kernel<<<gemm_grid, 256, GEMM_SMEM>>>(embed, proj, scale);

    bigram_gather_kernel<<<N_TOKENS / 4, 512>>>(tok, out, tok_stride);
}

// round 13
// speedup vs baseline: 1.0868x; 1.0868x over previous
#include <cuda_runtime.h>
#include <cuda_bf16.h>
#include <cstdint>

#define HASH_SIZE 10240
#define HMOD      10239
#define PROJ_DIM  128
#define MODEL_DIM 512
#define N_TOKENS  (8 * 8192)

// 21 MB scratch: projected embedding table P[hash][model_dim].
// Written by kernel 1 with default (L2-allocating) stores; read by kernel 2
// as L2 hits. Do NOT stream these stores.
__device__ float g_P[HASH_SIZE * MODEL_DIM];

// packed fp32x2 FMA (sm_100+ PTX only; ptxas never auto-fuses this)
__device__ __forceinline__ void ffma2(unsigned long long& d,
                                      unsigned long long a,
                                      unsigned long long b) {
    asm("fma.rn.f32x2 %0, %1, %2, %0;" : "+l"(d) : "l"(a), "l"(b));
}

// ---------------------------------------------------------------------------
// Kernel 1: P[h][m] = scale * sum_k embed[h][k] * proj[m][k]
// Block tile 128(h) x 64(m), 256 threads, thread tile 8x4, f32x2-packed K.
// Per warp per k-pair: 32 FFMA2 vs 12 LDS.64 (a: 2-addr broadcast, b: 16
// distinct 8B) -> per-SM crossbar 192 cyc vs fma 256 cyc -> FFMA-bound.
// ---------------------------------------------------------------------------
#define TILE_H    128
#define TILE_M    64
#define ROWPAD    130
#define GEMM_SMEM ((TILE_H + TILE_M) * ROWPAD * (int)sizeof(float))

__global__ __launch_bounds__(256, 2) void bigram_gemm_kernel(
    const float* __restrict__ A, const float* __restrict__ B,
    const float* __restrict__ scale_p) {
    extern __shared__ float smem[];
    float(*As)[ROWPAD] = (float(*)[ROWPAD])smem;
    float(*Bs)[ROWPAD] = (float(*)[ROWPAD])(smem + TILE_H * ROWPAD);

    const int tid = threadIdx.x;
    const int h0  = blockIdx.x * TILE_H;
    const int m0  = blockIdx.y * TILE_M;

    for (int i = tid; i < TILE_H * (PROJ_DIM / 4); i += 256) {
        int r = i >> 5, c = i & 31;
        float4 v = __ldg(&((const float4*)(A + (size_t)(h0 + r) * PROJ_DIM))[c]);
        As[r][c * 4 + 0] = v.x; As[r][c * 4 + 1] = v.y;
        As[r][c * 4 + 2] = v.z; As[r][c * 4 + 3] = v.w;
    }
    for (int i = tid; i < TILE_M * (PROJ_DIM / 4); i += 256) {
        int r = i >> 5, c = i & 31;
        float4 v = __ldg(&((const float4*)(B + (size_t)(m0 + r) * PROJ_DIM))[c]);
        Bs[r][c * 4 + 0] = v.x; Bs[r][c * 4 + 1] = v.y;
        Bs[r][c * 4 + 2] = v.z; Bs[r][c * 4 + 3] = v.w;
    }
    __syncthreads();

    const int tx = tid & 15;   // m: m0 + tx + 16*j, j<4
    const int ty = tid >> 4;   // h: h0 + ty + 16*i, i<8

    unsigned long long acc[8][4];
#pragma unroll
    for (int i = 0; i < 8; i++)
#pragma unroll
        for (int j = 0; j < 4; j++) acc[i][j] = 0ULL;

#pragma unroll 4
    for (int kp = 0; kp < PROJ_DIM / 2; ++kp) {
        unsigned long long a[8], b[4];
#pragma unroll
        for (int j = 0; j < 4; j++)
            b[j] = *(const unsigned long long*)&Bs[tx + 16 * j][2 * kp];
#pragma unroll
        for (int i = 0; i < 8; i++)
            a[i] = *(const unsigned long long*)&As[ty + 16 * i][2 * kp];
#pragma unroll
        for (int i = 0; i < 8; i++)
#pragma unroll
            for (int j = 0; j < 4; j++) ffma2(acc[i][j], a[i], b[j]);
    }

    const float s = __ldg(scale_p);
#pragma unroll
    for (int i = 0; i < 8; i++) {
        const int h = h0 + ty + 16 * i;
#pragma unroll
        for (int j = 0; j < 4; j++) {
            const int m = m0 + tx + 16 * j;
            union { unsigned long long u; float2 f; } cvt;
            cvt.u = acc[i][j];
            g_P[(size_t)h * MODEL_DIM + m] = (cvt.f.x + cvt.f.y) * s;
        }
    }
}

// ---------------------------------------------------------------------------
// Kernel 2: hash + gather, MLP-8 edition.
// R12 ncu showed 36.9us with NO pipe saturated (DRAM 33%, L2 38%, issue 28%)
// -> latency-bound: each thread had ONE dependent chain (MLP=1).
// Now: one warp owns 2 consecutive tokens. Each lane issues 8 INDEPENDENT
// float4 loads (4 per token row, 512B apart) back-to-back, then 8 stores.
// 48 warps/SM x 8 outstanding loads covers the ~240cyc L2-hit latency ->
// becomes genuinely LTS-bound: 268MB / ~6300 B/cyc ~= 20us.
// tokenA is even -> tokenB = tokenA+1 never has s==0.
// ---------------------------------------------------------------------------
__global__ __launch_bounds__(256) void bigram_gather_kernel(
    const int* __restrict__ tok, float* __restrict__ out, int tok_stride) {
    const int warp = threadIdx.x >> 5;
    const int lane = threadIdx.x & 31;
    const int tokenA = (blockIdx.x * 8 + warp) * 2;   // even
    const int tokenB = tokenA + 1;
    const int sA = tokenA & 8191;                     // S = 8192

    // 3 distinct token loads (broadcast within warp, tiny L1 footprint)
    const int tA  = __ldg(&tok[(size_t)tokenA * tok_stride]);
    const int tB  = __ldg(&tok[(size_t)tokenB * tok_stride]);
    const int tAm = (sA == 0) ? 0 : __ldg(&tok[(size_t)(tokenA - 1) * tok_stride]);

    // 36313*t, 27191*t < 2^31 for t < 50257 -> no overflow; xor >= 0 -> % == jnp.mod
    const int hA = (sA == 0) ? HMOD : (36313 * tA ^ 27191 * tAm) % HMOD;
    const int hB = (36313 * tB ^ 27191 * tA) % HMOD;

    const float4* __restrict__ pA = (const float4*)&g_P[(size_t)hA * MODEL_DIM];
    const float4* __restrict__ pB = (const float4*)&g_P[(size_t)hB * MODEL_DIM];

    // 8 independent loads, issued back-to-back (MLP = 8)
    float4 a0 = __ldg(&pA[lane      ]);
    float4 a1 = __ldg(&pA[lane + 32 ]);
    float4 a2 = __ldg(&pA[lane + 64 ]);
    float4 a3 = __ldg(&pA[lane + 96 ]);
    float4 b0 = __ldg(&pB[lane      ]);
    float4 b1 = __ldg(&pB[lane + 32 ]);
    float4 b2 = __ldg(&pB[lane + 64 ]);
    float4 b3 = __ldg(&pB[lane + 96 ]);

    float4* oA = (float4*)&out[(size_t)tokenA * MODEL_DIM];
    float4* oB = (float4*)&out[(size_t)tokenB * MODEL_DIM];
    __stcs(&oA[lane      ], a0);
    __stcs(&oA[lane + 32 ], a1);
    __stcs(&oA[lane + 64 ], a2);
    __stcs(&oA[lane + 96 ], a3);
    __stcs(&oB[lane      ], b0);
    __stcs(&oB[lane + 32 ], b1);
    __stcs(&oB[lane + 64 ], b2);
    __stcs(&oB[lane + 96 ], b3);
}

// ---------------------------------------------------------------------------
extern "C" void kernel_launch(void* const* d_in, const int* in_sizes, int n_in,
                              void* d_out, int out_size) {
    const int*   tok   = (const int*)d_in[0];   // [8,8192] int32 (or int64)
    const float* embed = (const float*)d_in[1]; // [10240,128] f32
    const float* proj  = (const float*)d_in[2]; // [512,128] f32
    const float* scale = (const float*)d_in[3]; // scalar f32
    float*       out   = (float*)d_out;         // [8,8192,512] f32

    const int tok_stride = (in_sizes[0] >= 2 * N_TOKENS) ? 2 : 1;

    cudaFuncSetAttribute(bigram_gemm_kernel,
                         cudaFuncAttributeMaxDynamicSharedMemorySize,
                         GEMM_SMEM);

    dim3 gemm_grid(HASH_SIZE / TILE_H, MODEL_DIM / TILE_M);  // 80 x 8
    bigram_gemm_kernel<<<gemm_grid, 256, GEMM_SMEM>>>(embed, proj, scale);

    // 16 tokens per 256-thread block (2 per warp) -> 4096 blocks
    bigram_gather_kernel<<<N_TOKENS / 16, 256>>>(tok, out, tok_stride);
}